// round 4
// baseline (speedup 1.0000x reference)
#include <cuda_runtime.h>
#include <cuda_bf16.h>
#include <cfloat>
#include <math.h>

// Problem dims (fixed by the dataset)
#define BN   2048   // batch B
#define DN   128    // feature dim D (also #decoders and output dim)
#define HN   512    // hidden H
#define KP1  513    // HN + 1 prefix rows

// ---------------------------------------------------------------------------
// Scratch (device globals; no allocation allowed)
// ---------------------------------------------------------------------------
__device__ float g_ench [BN * HN];              // leaky(x@We1^T+be1)        4 MB
__device__ float g_enc  [BN * DN];              // encoded (B,D)             1 MB
__device__ float g_W2T  [(size_t)DN * HN * DN]; // W2 transposed [j][h][d]  33.5 MB
__device__ float g_ts   [DN * HN];              // sorted breakpoint keys
__device__ int   g_sidx [DN * HN];              // sort order (h index)
__device__ float g_slope[(size_t)DN * KP1 * DN];// [j][k][d]                33.6 MB
__device__ float g_offs [(size_t)DN * KP1 * DN];// [j][k][d]                33.6 MB
__device__ int   g_rank [DN * BN];              // [j][b]
__device__ float g_zt   [DN * BN];              // z[j][b] = encoded[b][j]

// ---------------------------------------------------------------------------
// Classification of breakpoint h: "finite" kink vs constant contribution
// ---------------------------------------------------------------------------
__device__ __forceinline__ bool finite_case(float w1, float t) {
    return (w1 != 0.0f) && isfinite(t);
}

// ---------------------------------------------------------------------------
// Kernel 1/2: encoder GEMMs   C[m,n] = act(bias[n] + sum_k A[m,k]*B[n,k])
// A: [M,K] row-major, B: [N,K] row-major. 64x64 tiles, 4x4 micro, TK=32.
// ACT: 0 = leaky(0.2), 1 = tanh
// ---------------------------------------------------------------------------
template<int ACT>
__global__ void gemm_bias_act(const float* __restrict__ A,
                              const float* __restrict__ Bm,
                              const float* __restrict__ bias,
                              float* __restrict__ C,
                              int M, int N, int K)
{
    __shared__ float As[64][33];
    __shared__ float Bs[64][33];

    const int tid = threadIdx.x;
    const int tx = tid & 15;          // n direction
    const int ty = tid >> 4;          // m direction
    const int bm = blockIdx.y * 64;
    const int bn = blockIdx.x * 64;

    float acc[4][4];
#pragma unroll
    for (int i = 0; i < 4; i++)
#pragma unroll
        for (int j = 0; j < 4; j++) acc[i][j] = 0.0f;

    for (int kc = 0; kc < K; kc += 32) {
        // stage A tile (64 x 32) and B tile (64 x 32), coalesced
#pragma unroll
        for (int l = 0; l < 8; l++) {
            int idx = tid + 256 * l;
            int r = idx >> 5, c = idx & 31;
            As[r][c] = A[(size_t)(bm + r) * K + kc + c];
            Bs[r][c] = Bm[(size_t)(bn + r) * K + kc + c];
        }
        __syncthreads();
#pragma unroll
        for (int kk = 0; kk < 32; kk++) {
            float a[4], b[4];
#pragma unroll
            for (int i = 0; i < 4; i++) a[i] = As[ty * 4 + i][kk];
#pragma unroll
            for (int j = 0; j < 4; j++) b[j] = Bs[tx * 4 + j][kk];
#pragma unroll
            for (int i = 0; i < 4; i++)
#pragma unroll
                for (int j = 0; j < 4; j++)
                    acc[i][j] = fmaf(a[i], b[j], acc[i][j]);
        }
        __syncthreads();
    }

#pragma unroll
    for (int i = 0; i < 4; i++) {
        int m = bm + ty * 4 + i;
#pragma unroll
        for (int j = 0; j < 4; j++) {
            int n = bn + tx * 4 + j;
            float v = acc[i][j] + bias[n];
            if (ACT == 0) v = (v >= 0.0f) ? v : 0.2f * v;
            else          v = tanhf(v);
            C[(size_t)m * N + n] = v;
        }
    }
}

// ---------------------------------------------------------------------------
// Kernel 3: per-j bitonic sort of 512 breakpoints  (block = j, 512 threads)
// ---------------------------------------------------------------------------
__global__ void sort_breakpoints(const float* __restrict__ W1s,
                                 const float* __restrict__ b1s)
{
    __shared__ float key[HN];
    __shared__ int   idx[HN];
    const int j = blockIdx.x;
    const int h = threadIdx.x;

    float w1 = W1s[j * HN + h];
    float b1 = b1s[j * HN + h];
    float t  = -b1 / w1;
    key[h] = finite_case(w1, t) ? t : FLT_MAX;
    idx[h] = h;
    __syncthreads();

    for (int size = 2; size <= HN; size <<= 1) {
        for (int stride = size >> 1; stride > 0; stride >>= 1) {
            int p = h ^ stride;
            if (p > h) {
                bool asc = ((h & size) == 0);
                float kh = key[h], kp = key[p];
                if ((kh > kp) == asc) {
                    key[h] = kp; key[p] = kh;
                    int th = idx[h]; idx[h] = idx[p]; idx[p] = th;
                }
            }
            __syncthreads();
        }
    }
    g_ts  [j * HN + h] = key[h];
    g_sidx[j * HN + h] = idx[h];
}

// ---------------------------------------------------------------------------
// Kernel 4: transpose W2s per decoder:  W2T[j][h][d] = W2s[j][d][h]
// ---------------------------------------------------------------------------
__global__ void transpose_w2(const float* __restrict__ W2s)
{
    __shared__ float tile[32][33];
    const int j  = blockIdx.z;
    const int hb = blockIdx.x * 32;
    const int db = blockIdx.y * 32;
    const int tx = threadIdx.x;           // 0..31
    const int ty = threadIdx.y;           // 0..7

#pragma unroll
    for (int dy = 0; dy < 4; dy++) {
        int d = db + ty + dy * 8;
        tile[ty + dy * 8][tx] = W2s[((size_t)j * DN + d) * HN + hb + tx];
    }
    __syncthreads();
#pragma unroll
    for (int dy = 0; dy < 4; dy++) {
        int h = hb + ty + dy * 8;
        g_W2T[((size_t)j * HN + h) * DN + db + tx] = tile[tx][ty + dy * 8];
    }
}

// ---------------------------------------------------------------------------
// Kernel 5: build SLOPE/OFFS tables.  block = j, 128 threads (one per d).
//
// terms[j,b,d] = SLOPE[j,k,d]*z + OFFS[j,k,d],  k = #{h : t_h <= z}
//  SLOPE[k] = 0.6*A - Gtot + 2*P_k
//  OFFS [k] = 0.6*C + Qtot + Xtra + b2 - 2*Q_k
// with A=sum w1*w2, C=sum b1*w2, gamma=0.4*|w1|*w2,
// Gtot/Qtot totals of gamma / gamma*t, P_k/Q_k prefixes in sorted order,
// Xtra = sum over degenerate h of 0.4*|b1|*w2.
// ---------------------------------------------------------------------------
__global__ void build_tables(const float* __restrict__ W1s,
                             const float* __restrict__ b1s,
                             const float* __restrict__ b2s)
{
    __shared__ float w1_s[HN];
    __shared__ float b1_s[HN];
    __shared__ int   idx_s[HN];

    const int j = blockIdx.x;
    const int d = threadIdx.x;

    for (int i = threadIdx.x; i < HN; i += DN) {
        w1_s[i]  = W1s[j * HN + i];
        b1_s[i]  = b1s[j * HN + i];
        idx_s[i] = g_sidx[j * HN + i];
    }
    __syncthreads();

    const float* __restrict__ wrow = g_W2T + (size_t)j * HN * DN;

    // Pass 1: totals (coalesced, natural h order)
    float A = 0.f, C = 0.f, G = 0.f, Qt = 0.f, X = 0.f;
    for (int h = 0; h < HN; h++) {
        float w2 = wrow[h * DN + d];
        float w1 = w1_s[h], b1 = b1_s[h];
        A = fmaf(w1, w2, A);
        C = fmaf(b1, w2, C);
        float t = -b1 / w1;
        if (finite_case(w1, t)) {
            float g = 0.4f * fabsf(w1) * w2;
            G += g;
            Qt = fmaf(g, t, Qt);
        } else {
            X = fmaf(0.4f * fabsf(b1), w2, X);
        }
    }

    const float base_s = 0.6f * A - G;
    const float base_o = 0.6f * C + Qt + X + b2s[j * DN + d];
    const size_t orow = (size_t)j * KP1 * DN + d;
    g_slope[orow] = base_s;
    g_offs [orow] = base_o;

    // Pass 2: prefixes in sorted order (gathered rows, L2-warm)
    float P = 0.f, Q2 = 0.f;
    for (int k = 1; k <= HN; k++) {
        int h = idx_s[k - 1];
        float w1 = w1_s[h], b1 = b1_s[h];
        float t = -b1 / w1;
        if (finite_case(w1, t)) {
            float w2 = wrow[h * DN + d];
            float g = 0.4f * fabsf(w1) * w2;
            P += g;
            Q2 = fmaf(g, t, Q2);
        }
        g_slope[orow + (size_t)k * DN] = base_s + 2.0f * P;
        g_offs [orow + (size_t)k * DN] = base_o - 2.0f * Q2;
    }
}

// ---------------------------------------------------------------------------
// Kernel 6: rank(z) per (j,b) via binary search (upper bound)
// ---------------------------------------------------------------------------
__global__ void rank_kernel()
{
    int gid = blockIdx.x * blockDim.x + threadIdx.x;
    if (gid >= DN * BN) return;
    int j = gid >> 11;          // /2048
    int b = gid & (BN - 1);
    float z = g_enc[b * DN + j];
    const float* __restrict__ ts = g_ts + j * HN;
    int lo = 0, hi = HN;
    while (lo < hi) {
        int mid = (lo + hi) >> 1;
        if (ts[mid] <= z) lo = mid + 1; else hi = mid;
    }
    g_rank[gid] = lo;
    g_zt  [gid] = z;
}

// ---------------------------------------------------------------------------
// Kernel 7: evaluate + cumsum + tanh.
// block = 16 b's (one warp per b), warp lanes cover d via float4.
// acc[b,d] lives in registers; j loop is the inclusive prefix sum.
// ---------------------------------------------------------------------------
__global__ __launch_bounds__(512) void eval_kernel(float* __restrict__ out)
{
    __shared__ float z_s[DN][16];
    __shared__ int   k_s[DN][16];

    const int b0   = blockIdx.x * 16;
    const int w    = threadIdx.x >> 5;     // warp -> b_local
    const int lane = threadIdx.x & 31;     // lane -> d quad

    // stage z / rank for this b-tile
    for (int i = threadIdx.x; i < DN * 16; i += 512) {
        int jj = i >> 4, bl = i & 15;
        z_s[jj][bl] = g_zt  [jj * BN + b0 + bl];
        k_s[jj][bl] = g_rank[jj * BN + b0 + bl];
    }
    __syncthreads();

    const int b = b0 + w;
    float4 acc = make_float4(0.f, 0.f, 0.f, 0.f);

#pragma unroll 4
    for (int j = 0; j < DN; j++) {
        float z = z_s[j][w];
        int   k = k_s[j][w];
        size_t row = ((size_t)(j * KP1 + k)) * DN + lane * 4;
        float4 sl = *reinterpret_cast<const float4*>(g_slope + row);
        float4 of = *reinterpret_cast<const float4*>(g_offs  + row);
        // term = slope*z + offs (rounded like the reference), then accumulate
        acc.x += fmaf(sl.x, z, of.x);
        acc.y += fmaf(sl.y, z, of.y);
        acc.z += fmaf(sl.z, z, of.z);
        acc.w += fmaf(sl.w, z, of.w);
        float4 o;
        o.x = tanhf(acc.x); o.y = tanhf(acc.y);
        o.z = tanhf(acc.z); o.w = tanhf(acc.w);
        *reinterpret_cast<float4*>(out + ((size_t)j * BN + b) * DN + lane * 4) = o;
    }
}

// ---------------------------------------------------------------------------
// Launch
// ---------------------------------------------------------------------------
extern "C" void kernel_launch(void* const* d_in, const int* in_sizes, int n_in,
                              void* d_out, int out_size)
{
    const float* x   = (const float*)d_in[0];   // (2048,128)
    const float* We1 = (const float*)d_in[1];   // (512,128)
    const float* be1 = (const float*)d_in[2];   // (512,)
    const float* We2 = (const float*)d_in[3];   // (128,512)
    const float* be2 = (const float*)d_in[4];   // (128,)
    const float* W1s = (const float*)d_in[5];   // (128,512)
    const float* b1s = (const float*)d_in[6];   // (128,512)
    const float* W2s = (const float*)d_in[7];   // (128,128,512)
    const float* b2s = (const float*)d_in[8];   // (128,128)
    float* out = (float*)d_out;                 // (128,2048,128)

    float* ench; cudaGetSymbolAddress((void**)&ench, g_ench);
    float* enc;  cudaGetSymbolAddress((void**)&enc,  g_enc);

    // Encoder
    gemm_bias_act<0><<<dim3(HN / 64, BN / 64), 256>>>(x,    We1, be1, ench, BN, HN, DN);
    gemm_bias_act<1><<<dim3(DN / 64, BN / 64), 256>>>(ench, We2, be2, enc,  BN, DN, HN);

    // Piecewise-linear table construction (independent of encoder)
    sort_breakpoints<<<DN, HN>>>(W1s, b1s);
    transpose_w2<<<dim3(HN / 32, DN / 32, DN), dim3(32, 8)>>>(W2s);
    build_tables<<<DN, DN>>>(W1s, b1s, b2s);

    // Rank lookup, then fused eval + cumsum + tanh
    rank_kernel<<<(DN * BN) / 256, 256>>>();
    eval_kernel<<<BN / 16, 512>>>(out);
}

// round 5
// speedup vs baseline: 2.1841x; 2.1841x over previous
#include <cuda_runtime.h>
#include <cuda_bf16.h>
#include <cfloat>
#include <math.h>

// Problem dims (fixed by the dataset)
#define BN   2048   // batch B
#define DN   128    // feature dim D (also #decoders and output dim)
#define HN   512    // hidden H
#define KP1  513    // HN + 1 prefix rows

// ---------------------------------------------------------------------------
// Scratch (device globals; no allocation allowed)
// ---------------------------------------------------------------------------
__device__ float g_ench [BN * HN];               // leaky(x@We1^T+be1)
__device__ float g_enc  [BN * DN];               // encoded (B,D)
__device__ float g_W2srt[(size_t)DN * HN * DN];  // W2 gathered: [j][k][d]   33.5 MB
__device__ float g_ts   [DN * HN];               // sorted breakpoint keys
__device__ int   g_pos  [DN * HN];               // pos[h] = sorted rank of h
__device__ float g_sg   [DN * HN];               // sorted 0.4|w1| (0 if degen)
__device__ float g_sgt  [DN * HN];               // sorted 0.4|w1|*t
__device__ float g_sw1  [DN * HN];               // sorted w1
__device__ float g_sb1  [DN * HN];               // sorted b1
__device__ float g_sx   [DN * HN];               // sorted degen 0.4|b1|
__device__ float g_tab  [(size_t)DN * KP1 * 2 * DN]; // interleaved (slope,offs) 67 MB
__device__ int   g_rank [DN * BN];               // [j][b]
__device__ float g_zt   [DN * BN];               // z[j][b]

__device__ __forceinline__ float tanh_fast(float x) {
    float y;
    asm("tanh.approx.f32 %0, %1;" : "=f"(y) : "f"(x));
    return y;
}

// ---------------------------------------------------------------------------
// Kernel 1/2: encoder GEMMs   C[m,n] = act(bias[n] + sum_k A[m,k]*B[n,k])
// ACT: 0 = leaky(0.2), 1 = tanh (accurate — error would propagate)
// ---------------------------------------------------------------------------
template<int ACT>
__global__ void gemm_bias_act(const float* __restrict__ A,
                              const float* __restrict__ Bm,
                              const float* __restrict__ bias,
                              float* __restrict__ C,
                              int M, int N, int K)
{
    __shared__ float As[64][33];
    __shared__ float Bs[64][33];

    const int tid = threadIdx.x;
    const int tx = tid & 15;          // n direction
    const int ty = tid >> 4;          // m direction
    const int bm = blockIdx.y * 64;
    const int bn = blockIdx.x * 64;

    float acc[4][4];
#pragma unroll
    for (int i = 0; i < 4; i++)
#pragma unroll
        for (int j = 0; j < 4; j++) acc[i][j] = 0.0f;

    for (int kc = 0; kc < K; kc += 32) {
#pragma unroll
        for (int l = 0; l < 8; l++) {
            int idx = tid + 256 * l;
            int r = idx >> 5, c = idx & 31;
            As[r][c] = A[(size_t)(bm + r) * K + kc + c];
            Bs[r][c] = Bm[(size_t)(bn + r) * K + kc + c];
        }
        __syncthreads();
#pragma unroll
        for (int kk = 0; kk < 32; kk++) {
            float a[4], b[4];
#pragma unroll
            for (int i = 0; i < 4; i++) a[i] = As[ty * 4 + i][kk];
#pragma unroll
            for (int j = 0; j < 4; j++) b[j] = Bs[tx * 4 + j][kk];
#pragma unroll
            for (int i = 0; i < 4; i++)
#pragma unroll
                for (int j = 0; j < 4; j++)
                    acc[i][j] = fmaf(a[i], b[j], acc[i][j]);
        }
        __syncthreads();
    }

#pragma unroll
    for (int i = 0; i < 4; i++) {
        int m = bm + ty * 4 + i;
#pragma unroll
        for (int j = 0; j < 4; j++) {
            int n = bn + tx * 4 + j;
            float v = acc[i][j] + bias[n];
            if (ACT == 0) v = (v >= 0.0f) ? v : 0.2f * v;
            else          v = tanhf(v);
            C[(size_t)m * N + n] = v;
        }
    }
}

// ---------------------------------------------------------------------------
// Kernel 3: per-j bitonic sort of 512 breakpoints; emit sorted scalar arrays
// and inverse permutation.
// ---------------------------------------------------------------------------
__global__ void sort_breakpoints(const float* __restrict__ W1s,
                                 const float* __restrict__ b1s)
{
    __shared__ float key[HN];
    __shared__ int   idx[HN];
    const int j = blockIdx.x;
    const int h = threadIdx.x;

    float w1 = W1s[j * HN + h];
    float b1 = b1s[j * HN + h];
    float t  = -b1 / w1;
    bool fin = (w1 != 0.0f) && isfinite(t);
    key[h] = fin ? t : FLT_MAX;
    idx[h] = h;
    __syncthreads();

    for (int size = 2; size <= HN; size <<= 1) {
        for (int stride = size >> 1; stride > 0; stride >>= 1) {
            int p = h ^ stride;
            if (p > h) {
                bool asc = ((h & size) == 0);
                float kh = key[h], kp = key[p];
                if ((kh > kp) == asc) {
                    key[h] = kp; key[p] = kh;
                    int th = idx[h]; idx[h] = idx[p]; idx[p] = th;
                }
            }
            __syncthreads();
        }
    }
    // position h in sorted order holds original index idx[h]
    float tk  = key[h];
    int   ho  = idx[h];
    float w1o = W1s[j * HN + ho];
    float b1o = b1s[j * HN + ho];
    bool  fo  = (tk != FLT_MAX);

    g_ts [j * HN + h]  = tk;
    g_pos[j * HN + ho] = h;
    g_sw1[j * HN + h]  = w1o;
    g_sb1[j * HN + h]  = b1o;
    float sg = fo ? 0.4f * fabsf(w1o) : 0.0f;
    g_sg [j * HN + h]  = sg;
    g_sgt[j * HN + h]  = fo ? sg * tk : 0.0f;
    g_sx [j * HN + h]  = fo ? 0.0f : 0.4f * fabsf(b1o);
}

// ---------------------------------------------------------------------------
// Kernel 4: fused transpose + sorted gather:
//   W2srt[j][pos[h]][d] = W2s[j][d][h]
// ---------------------------------------------------------------------------
__global__ void gather_transpose(const float* __restrict__ W2s)
{
    __shared__ float tile[DN][33];   // [d][h_local]
    const int j  = blockIdx.z;
    const int hb = blockIdx.x * 32;
    const int tx = threadIdx.x;      // 0..31
    const int ty = threadIdx.y;      // 0..7

    // load coalesced along h; smem write tile[d][tx] consecutive -> no conflict
#pragma unroll
    for (int d = ty; d < DN; d += 8)
        tile[d][tx] = W2s[((size_t)j * DN + d) * HN + hb + tx];
    __syncthreads();

    // warp ty writes h rows {ty, ty+8, ty+16, ty+24}; lane covers d strided
#pragma unroll
    for (int r = 0; r < 4; r++) {
        int h = ty + r * 8;
        int k = g_pos[j * HN + hb + h];
        float* orow = g_W2srt + ((size_t)j * HN + k) * DN;
#pragma unroll
        for (int db = 0; db < 4; db++) {
            // smem read stride 33 words across lanes -> conflict-free
            orow[db * 32 + tx] = tile[db * 32 + tx][h];
        }
    }
}

// ---------------------------------------------------------------------------
// Kernel 5: build interleaved table  tab[j][k][2d] = slope, tab[j][k][2d+1] = offs
// Parallel chunked prefix scan: threads = (d:128, c:8), chunk length 64.
// ---------------------------------------------------------------------------
__global__ __launch_bounds__(1024) void build_tables(const float* __restrict__ b2s)
{
    __shared__ float sg_s[HN], sgt_s[HN], sw1_s[HN], sb1_s[HN], sx_s[HN];
    __shared__ float pg[8][DN], pq[8][DN], pa[8][DN], pc[8][DN], px[8][DN];

    const int j   = blockIdx.x;
    const int tid = threadIdx.x;
    const int d   = tid & 127;
    const int c   = tid >> 7;

    for (int i = tid; i < HN; i += 1024) {
        sg_s [i] = g_sg [j * HN + i];
        sgt_s[i] = g_sgt[j * HN + i];
        sw1_s[i] = g_sw1[j * HN + i];
        sb1_s[i] = g_sb1[j * HN + i];
        sx_s [i] = g_sx [j * HN + i];
    }
    __syncthreads();

    const float* __restrict__ wrow = g_W2srt + (size_t)j * HN * DN;
    const int k0 = c * 64;

    // Phase A: chunk partial sums (fully coalesced, 8 concurrent streams)
    float ga = 0.f, qa = 0.f, aa = 0.f, ca = 0.f, xa = 0.f;
#pragma unroll 8
    for (int i = 0; i < 64; i++) {
        int kk = k0 + i;
        float w2 = wrow[kk * DN + d];
        ga = fmaf(sg_s [kk], w2, ga);
        qa = fmaf(sgt_s[kk], w2, qa);
        aa = fmaf(sw1_s[kk], w2, aa);
        ca = fmaf(sb1_s[kk], w2, ca);
        xa = fmaf(sx_s [kk], w2, xa);
    }
    pg[c][d] = ga; pq[c][d] = qa; pa[c][d] = aa; pc[c][d] = ca; px[c][d] = xa;
    __syncthreads();

    // Totals + carry-in for this chunk
    float A = 0.f, C = 0.f, G = 0.f, Qt = 0.f, X = 0.f, Pcar = 0.f, Qcar = 0.f;
#pragma unroll
    for (int cc = 0; cc < 8; cc++) {
        float g = pg[cc][d], q = pq[cc][d];
        A += pa[cc][d]; C += pc[cc][d]; X += px[cc][d];
        G += g; Qt += q;
        if (cc < c) { Pcar += g; Qcar += q; }
    }

    const float base_s = 0.6f * A - G;
    const float base_o = 0.6f * C + Qt + X + b2s[j * DN + d];
    float* __restrict__ tj = g_tab + (size_t)j * KP1 * (2 * DN);
    if (c == 0) {
        *reinterpret_cast<float2*>(tj + 2 * d) = make_float2(base_s, base_o);
    }

    // Phase B: write 64 rows per chunk (re-reads are L2-hot)
    float P = Pcar, Q = Qcar;
#pragma unroll 8
    for (int i = 0; i < 64; i++) {
        int kk = k0 + i;
        float w2 = wrow[kk * DN + d];
        P = fmaf(sg_s [kk], w2, P);
        Q = fmaf(sgt_s[kk], w2, Q);
        float2 v = make_float2(fmaf(2.0f, P, base_s), fmaf(-2.0f, Q, base_o));
        *reinterpret_cast<float2*>(tj + (size_t)(kk + 1) * (2 * DN) + 2 * d) = v;
    }
}

// ---------------------------------------------------------------------------
// Kernel 6: rank(z) per (j,b), breakpoints staged in smem
// ---------------------------------------------------------------------------
__global__ __launch_bounds__(512) void rank_kernel()
{
    __shared__ float ts_s[HN];
    const int j = blockIdx.x;
    const int b = blockIdx.y * 512 + threadIdx.x;
    for (int i = threadIdx.x; i < HN; i += 512) ts_s[i] = g_ts[j * HN + i];
    __syncthreads();

    float z = g_enc[b * DN + j];
    int lo = 0, hi = HN;
    while (lo < hi) {
        int mid = (lo + hi) >> 1;
        if (ts_s[mid] <= z) lo = mid + 1; else hi = mid;
    }
    g_rank[j * BN + b] = lo;
    g_zt  [j * BN + b] = z;
}

// ---------------------------------------------------------------------------
// Kernel 7: evaluate + cumsum + tanh (HW tanh.approx).
// block = 8 b's (one warp per b); lane covers d pairs via float4 on the
// interleaved 1KB table rows.
// ---------------------------------------------------------------------------
__global__ __launch_bounds__(256) void eval_kernel(float* __restrict__ out)
{
    __shared__ float z_s[DN][8];
    __shared__ int   k_s[DN][8];

    const int b0   = blockIdx.x * 8;
    const int w    = threadIdx.x >> 5;     // warp -> b_local
    const int lane = threadIdx.x & 31;

    for (int i = threadIdx.x; i < DN * 8; i += 256) {
        int jj = i >> 3, bl = i & 7;
        z_s[jj][bl] = g_zt  [jj * BN + b0 + bl];
        k_s[jj][bl] = g_rank[jj * BN + b0 + bl];
    }
    __syncthreads();

    const int b = b0 + w;
    float a0 = 0.f, a1 = 0.f, a2 = 0.f, a3 = 0.f;

#pragma unroll 4
    for (int j = 0; j < DN; j++) {
        float z = z_s[j][w];
        int   k = k_s[j][w];
        const float* row = g_tab + (size_t)(j * KP1 + k) * (2 * DN);
        float4 u = *reinterpret_cast<const float4*>(row + 4 * lane);        // d = 2l, 2l+1
        float4 v = *reinterpret_cast<const float4*>(row + 128 + 4 * lane);  // d = 64+2l, 65+2l

        a0 += fmaf(u.x, z, u.y);
        a1 += fmaf(u.z, z, u.w);
        a2 += fmaf(v.x, z, v.y);
        a3 += fmaf(v.z, z, v.w);

        float* op = out + ((size_t)j * BN + b) * DN;
        *reinterpret_cast<float2*>(op + 2 * lane)      = make_float2(tanh_fast(a0), tanh_fast(a1));
        *reinterpret_cast<float2*>(op + 64 + 2 * lane) = make_float2(tanh_fast(a2), tanh_fast(a3));
    }
}

// ---------------------------------------------------------------------------
// Launch
// ---------------------------------------------------------------------------
extern "C" void kernel_launch(void* const* d_in, const int* in_sizes, int n_in,
                              void* d_out, int out_size)
{
    const float* x   = (const float*)d_in[0];   // (2048,128)
    const float* We1 = (const float*)d_in[1];   // (512,128)
    const float* be1 = (const float*)d_in[2];   // (512,)
    const float* We2 = (const float*)d_in[3];   // (128,512)
    const float* be2 = (const float*)d_in[4];   // (128,)
    const float* W1s = (const float*)d_in[5];   // (128,512)
    const float* b1s = (const float*)d_in[6];   // (128,512)
    const float* W2s = (const float*)d_in[7];   // (128,128,512)
    const float* b2s = (const float*)d_in[8];   // (128,128)
    float* out = (float*)d_out;                 // (128,2048,128)

    float* ench; cudaGetSymbolAddress((void**)&ench, g_ench);
    float* enc;  cudaGetSymbolAddress((void**)&enc,  g_enc);

    // Encoder
    gemm_bias_act<0><<<dim3(HN / 64, BN / 64), 256>>>(x,    We1, be1, ench, BN, HN, DN);
    gemm_bias_act<1><<<dim3(DN / 64, BN / 64), 256>>>(ench, We2, be2, enc,  BN, DN, HN);

    // Piecewise-linear table construction
    sort_breakpoints<<<DN, HN>>>(W1s, b1s);
    gather_transpose<<<dim3(HN / 32, 1, DN), dim3(32, 8)>>>(W2s);
    build_tables<<<DN, 1024>>>(b2s);

    // Rank lookup, then fused eval + cumsum + tanh
    rank_kernel<<<dim3(DN, BN / 512), 512>>>();
    eval_kernel<<<BN / 8, 256>>>(out);
}

// round 6
// speedup vs baseline: 2.2569x; 1.0333x over previous
#include <cuda_runtime.h>
#include <cuda_bf16.h>
#include <cfloat>
#include <math.h>

// Problem dims (fixed by the dataset)
#define BN   2048   // batch B
#define DN   128    // feature dim D (also #decoders and output dim)
#define HN   512    // hidden H
#define KP1  513    // HN + 1 prefix rows

// ---------------------------------------------------------------------------
// Scratch (device globals; no allocation allowed)
// ---------------------------------------------------------------------------
__device__ float g_ench [BN * HN];               // leaky(x@We1^T+be1)
__device__ float g_enc  [BN * DN];               // encoded (B,D)
__device__ float g_W2srt[(size_t)DN * HN * DN];  // W2 gathered: [j][k][d]   33.5 MB
__device__ float g_ts   [DN * HN];               // sorted breakpoint keys
__device__ int   g_pos  [DN * HN];               // pos[h] = sorted rank of h
__device__ float g_sg   [DN * HN];               // sorted 0.4|w1| (0 if degen)
__device__ float g_sgt  [DN * HN];               // sorted 0.4|w1|*t
__device__ float g_sw1  [DN * HN];               // sorted w1
__device__ float g_sb1  [DN * HN];               // sorted b1
__device__ float g_sx   [DN * HN];               // sorted degen 0.4|b1|
__device__ float g_tab  [(size_t)DN * KP1 * 2 * DN]; // interleaved (slope,offs) 67 MB
__device__ int   g_rank [DN * BN];               // [j][b]
__device__ float g_zt   [DN * BN];               // z[j][b]

__device__ __forceinline__ float tanh_fast(float x) {
    float y;
    asm("tanh.approx.f32 %0, %1;" : "=f"(y) : "f"(x));
    return y;
}

// ---------------------------------------------------------------------------
// Kernel 1/2: encoder GEMMs   C[m,n] = act(bias[n] + sum_k A[m,k]*B[n,k])
// ACT: 0 = leaky(0.2), 1 = tanh (accurate — error would propagate)
// ---------------------------------------------------------------------------
template<int ACT>
__global__ void gemm_bias_act(const float* __restrict__ A,
                              const float* __restrict__ Bm,
                              const float* __restrict__ bias,
                              float* __restrict__ C,
                              int M, int N, int K)
{
    __shared__ float As[64][33];
    __shared__ float Bs[64][33];

    const int tid = threadIdx.x;
    const int tx = tid & 15;          // n direction
    const int ty = tid >> 4;          // m direction
    const int bm = blockIdx.y * 64;
    const int bn = blockIdx.x * 64;

    float acc[4][4];
#pragma unroll
    for (int i = 0; i < 4; i++)
#pragma unroll
        for (int j = 0; j < 4; j++) acc[i][j] = 0.0f;

    for (int kc = 0; kc < K; kc += 32) {
#pragma unroll
        for (int l = 0; l < 8; l++) {
            int idx = tid + 256 * l;
            int r = idx >> 5, c = idx & 31;
            As[r][c] = A[(size_t)(bm + r) * K + kc + c];
            Bs[r][c] = Bm[(size_t)(bn + r) * K + kc + c];
        }
        __syncthreads();
#pragma unroll
        for (int kk = 0; kk < 32; kk++) {
            float a[4], b[4];
#pragma unroll
            for (int i = 0; i < 4; i++) a[i] = As[ty * 4 + i][kk];
#pragma unroll
            for (int j = 0; j < 4; j++) b[j] = Bs[tx * 4 + j][kk];
#pragma unroll
            for (int i = 0; i < 4; i++)
#pragma unroll
                for (int j = 0; j < 4; j++)
                    acc[i][j] = fmaf(a[i], b[j], acc[i][j]);
        }
        __syncthreads();
    }

#pragma unroll
    for (int i = 0; i < 4; i++) {
        int m = bm + ty * 4 + i;
#pragma unroll
        for (int j = 0; j < 4; j++) {
            int n = bn + tx * 4 + j;
            float v = acc[i][j] + bias[n];
            if (ACT == 0) v = (v >= 0.0f) ? v : 0.2f * v;
            else          v = tanhf(v);
            C[(size_t)m * N + n] = v;
        }
    }
}

// ---------------------------------------------------------------------------
// Kernel 3: per-j bitonic sort of 512 breakpoints; emit sorted scalar arrays
// and inverse permutation.
// ---------------------------------------------------------------------------
__global__ void sort_breakpoints(const float* __restrict__ W1s,
                                 const float* __restrict__ b1s)
{
    __shared__ float key[HN];
    __shared__ int   idx[HN];
    const int j = blockIdx.x;
    const int h = threadIdx.x;

    float w1 = W1s[j * HN + h];
    float b1 = b1s[j * HN + h];
    float t  = -b1 / w1;
    bool fin = (w1 != 0.0f) && isfinite(t);
    key[h] = fin ? t : FLT_MAX;
    idx[h] = h;
    __syncthreads();

    for (int size = 2; size <= HN; size <<= 1) {
        for (int stride = size >> 1; stride > 0; stride >>= 1) {
            int p = h ^ stride;
            if (p > h) {
                bool asc = ((h & size) == 0);
                float kh = key[h], kp = key[p];
                if ((kh > kp) == asc) {
                    key[h] = kp; key[p] = kh;
                    int th = idx[h]; idx[h] = idx[p]; idx[p] = th;
                }
            }
            __syncthreads();
        }
    }
    // position h in sorted order holds original index idx[h]
    float tk  = key[h];
    int   ho  = idx[h];
    float w1o = W1s[j * HN + ho];
    float b1o = b1s[j * HN + ho];
    bool  fo  = (tk != FLT_MAX);

    g_ts [j * HN + h]  = tk;
    g_pos[j * HN + ho] = h;
    g_sw1[j * HN + h]  = w1o;
    g_sb1[j * HN + h]  = b1o;
    float sg = fo ? 0.4f * fabsf(w1o) : 0.0f;
    g_sg [j * HN + h]  = sg;
    g_sgt[j * HN + h]  = fo ? sg * tk : 0.0f;
    g_sx [j * HN + h]  = fo ? 0.0f : 0.4f * fabsf(b1o);
}

// ---------------------------------------------------------------------------
// Kernel 4: fused transpose + sorted gather (128x128 tile, 66KB dyn smem):
//   W2srt[j][pos[h]][d] = W2s[j][d][h]
// Load: float4 along h (16 independent LDG.128/thread).
// Tile pitch 129 -> conflict-free scalar STS and LDS.
// Store: 4x coalesced 128B rows per k.
// ---------------------------------------------------------------------------
#define TP_PITCH 129
__global__ __launch_bounds__(256) void gather_transpose(const float* __restrict__ W2s)
{
    extern __shared__ float tile[];   // [128 d][TP_PITCH]
    const int j    = blockIdx.y;
    const int hb   = blockIdx.x * 128;
    const int tid  = threadIdx.x;
    const int w    = tid >> 5;
    const int lane = tid & 31;

    // Phase 1: load 128 d x 128 h as float4 along h
    const float4* src = reinterpret_cast<const float4*>(
        W2s + (size_t)j * DN * HN + hb);
#pragma unroll
    for (int l = 0; l < 16; l++) {
        int id = tid + 256 * l;          // 0..4095
        int d  = id >> 5;
        int hq = id & 31;
        float4 v = src[(size_t)d * (HN / 4) + hq];
        float* t = tile + d * TP_PITCH + hq * 4;
        t[0] = v.x; t[1] = v.y; t[2] = v.z; t[3] = v.w;
    }
    __syncthreads();

    // Phase 2: for each h row, write 128 d to the sorted-k destination row
    const int* pos = g_pos + j * HN + hb;
#pragma unroll
    for (int r = 0; r < 16; r++) {
        int h = r * 8 + w;
        int k = pos[h];
        float* orow = g_W2srt + ((size_t)j * HN + k) * DN;
#pragma unroll
        for (int c = 0; c < 4; c++)
            orow[c * 32 + lane] = tile[(c * 32 + lane) * TP_PITCH + h];
    }
}

// ---------------------------------------------------------------------------
// Kernel 5: build interleaved table  tab[j][k][2d] = slope, tab[j][k][2d+1] = offs
// Parallel chunked prefix scan: threads = (d:128, c:8), chunk length 64.
// ---------------------------------------------------------------------------
__global__ __launch_bounds__(1024) void build_tables(const float* __restrict__ b2s)
{
    __shared__ float sg_s[HN], sgt_s[HN], sw1_s[HN], sb1_s[HN], sx_s[HN];
    __shared__ float pg[8][DN], pq[8][DN], pa[8][DN], pc[8][DN], px[8][DN];

    const int j   = blockIdx.x;
    const int tid = threadIdx.x;
    const int d   = tid & 127;
    const int c   = tid >> 7;

    for (int i = tid; i < HN; i += 1024) {
        sg_s [i] = g_sg [j * HN + i];
        sgt_s[i] = g_sgt[j * HN + i];
        sw1_s[i] = g_sw1[j * HN + i];
        sb1_s[i] = g_sb1[j * HN + i];
        sx_s [i] = g_sx [j * HN + i];
    }
    __syncthreads();

    const float* __restrict__ wrow = g_W2srt + (size_t)j * HN * DN;
    const int k0 = c * 64;

    // Phase A: chunk partial sums (fully coalesced, 8 concurrent streams)
    float ga = 0.f, qa = 0.f, aa = 0.f, ca = 0.f, xa = 0.f;
#pragma unroll 8
    for (int i = 0; i < 64; i++) {
        int kk = k0 + i;
        float w2 = wrow[kk * DN + d];
        ga = fmaf(sg_s [kk], w2, ga);
        qa = fmaf(sgt_s[kk], w2, qa);
        aa = fmaf(sw1_s[kk], w2, aa);
        ca = fmaf(sb1_s[kk], w2, ca);
        xa = fmaf(sx_s [kk], w2, xa);
    }
    pg[c][d] = ga; pq[c][d] = qa; pa[c][d] = aa; pc[c][d] = ca; px[c][d] = xa;
    __syncthreads();

    // Totals + carry-in for this chunk
    float A = 0.f, C = 0.f, G = 0.f, Qt = 0.f, X = 0.f, Pcar = 0.f, Qcar = 0.f;
#pragma unroll
    for (int cc = 0; cc < 8; cc++) {
        float g = pg[cc][d], q = pq[cc][d];
        A += pa[cc][d]; C += pc[cc][d]; X += px[cc][d];
        G += g; Qt += q;
        if (cc < c) { Pcar += g; Qcar += q; }
    }

    const float base_s = 0.6f * A - G;
    const float base_o = 0.6f * C + Qt + X + b2s[j * DN + d];
    float* __restrict__ tj = g_tab + (size_t)j * KP1 * (2 * DN);
    if (c == 0) {
        *reinterpret_cast<float2*>(tj + 2 * d) = make_float2(base_s, base_o);
    }

    // Phase B: write 64 rows per chunk (re-reads are L2-hot)
    float P = Pcar, Q = Qcar;
#pragma unroll 8
    for (int i = 0; i < 64; i++) {
        int kk = k0 + i;
        float w2 = wrow[kk * DN + d];
        P = fmaf(sg_s [kk], w2, P);
        Q = fmaf(sgt_s[kk], w2, Q);
        float2 v = make_float2(fmaf(2.0f, P, base_s), fmaf(-2.0f, Q, base_o));
        *reinterpret_cast<float2*>(tj + (size_t)(kk + 1) * (2 * DN) + 2 * d) = v;
    }
}

// ---------------------------------------------------------------------------
// Kernel 6: rank(z) per (j,b), breakpoints staged in smem
// ---------------------------------------------------------------------------
__global__ __launch_bounds__(512) void rank_kernel()
{
    __shared__ float ts_s[HN];
    const int j = blockIdx.x;
    const int b = blockIdx.y * 512 + threadIdx.x;
    for (int i = threadIdx.x; i < HN; i += 512) ts_s[i] = g_ts[j * HN + i];
    __syncthreads();

    float z = g_enc[b * DN + j];
    int lo = 0, hi = HN;
    while (lo < hi) {
        int mid = (lo + hi) >> 1;
        if (ts_s[mid] <= z) lo = mid + 1; else hi = mid;
    }
    g_rank[j * BN + b] = lo;
    g_zt  [j * BN + b] = z;
}

// ---------------------------------------------------------------------------
// Kernel 7: evaluate + cumsum + tanh (HW tanh.approx).
// block = 4 b's, 8 warps: warp = (b_local, d-half). Each warp covers 64 d
// via one float4/lane/j on the interleaved 1KB table rows.
// grid = 512 blocks -> 4096 warps (2x R5 parallelism).
// ---------------------------------------------------------------------------
__global__ __launch_bounds__(256) void eval_kernel(float* __restrict__ out)
{
    __shared__ float z_s[DN][4];
    __shared__ int   k_s[DN][4];

    const int b0   = blockIdx.x * 4;
    const int w    = threadIdx.x >> 5;
    const int bl   = w >> 1;               // b_local 0..3
    const int half = w & 1;                // d-half 0/1
    const int lane = threadIdx.x & 31;

    for (int i = threadIdx.x; i < DN * 4; i += 256) {
        int jj = i >> 2, b2 = i & 3;
        z_s[jj][b2] = g_zt  [jj * BN + b0 + b2];
        k_s[jj][b2] = g_rank[jj * BN + b0 + b2];
    }
    __syncthreads();

    const int b = b0 + bl;
    const int toff = half * (DN) + lane * 4;     // offset into 256-float row
    float a0 = 0.f, a1 = 0.f;

#pragma unroll 4
    for (int j = 0; j < DN; j++) {
        float z = z_s[j][bl];
        int   k = k_s[j][bl];
        const float4 u = *reinterpret_cast<const float4*>(
            g_tab + (size_t)(j * KP1 + k) * (2 * DN) + toff);

        a0 += fmaf(u.x, z, u.y);
        a1 += fmaf(u.z, z, u.w);

        float* op = out + ((size_t)j * BN + b) * DN + half * 64 + 2 * lane;
        *reinterpret_cast<float2*>(op) = make_float2(tanh_fast(a0), tanh_fast(a1));
    }
}

// ---------------------------------------------------------------------------
// Launch
// ---------------------------------------------------------------------------
extern "C" void kernel_launch(void* const* d_in, const int* in_sizes, int n_in,
                              void* d_out, int out_size)
{
    const float* x   = (const float*)d_in[0];   // (2048,128)
    const float* We1 = (const float*)d_in[1];   // (512,128)
    const float* be1 = (const float*)d_in[2];   // (512,)
    const float* We2 = (const float*)d_in[3];   // (128,512)
    const float* be2 = (const float*)d_in[4];   // (128,)
    const float* W1s = (const float*)d_in[5];   // (128,512)
    const float* b1s = (const float*)d_in[6];   // (128,512)
    const float* W2s = (const float*)d_in[7];   // (128,128,512)
    const float* b2s = (const float*)d_in[8];   // (128,128)
    float* out = (float*)d_out;                 // (128,2048,128)

    float* ench; cudaGetSymbolAddress((void**)&ench, g_ench);
    float* enc;  cudaGetSymbolAddress((void**)&enc,  g_enc);

    // Encoder
    gemm_bias_act<0><<<dim3(HN / 64, BN / 64), 256>>>(x,    We1, be1, ench, BN, HN, DN);
    gemm_bias_act<1><<<dim3(DN / 64, BN / 64), 256>>>(ench, We2, be2, enc,  BN, DN, HN);

    // Piecewise-linear table construction
    sort_breakpoints<<<DN, HN>>>(W1s, b1s);

    const int tp_smem = DN * TP_PITCH * (int)sizeof(float);   // 66048 B
    cudaFuncSetAttribute(gather_transpose,
                         cudaFuncAttributeMaxDynamicSharedMemorySize, tp_smem);
    gather_transpose<<<dim3(HN / 128, DN), 256, tp_smem>>>(W2s);

    build_tables<<<DN, 1024>>>(b2s);

    // Rank lookup, then fused eval + cumsum + tanh
    rank_kernel<<<dim3(DN, BN / 512), 512>>>();
    eval_kernel<<<BN / 4, 256>>>(out);
}

// round 7
// speedup vs baseline: 2.8595x; 1.2670x over previous
#include <cuda_runtime.h>
#include <cuda_bf16.h>
#include <cfloat>
#include <math.h>

// Problem dims (fixed by the dataset)
#define BN   2048   // batch B
#define DN   128    // feature dim D (also #decoders and output dim)
#define HN   512    // hidden H
#define KP1  513    // HN + 1 prefix rows

// ---------------------------------------------------------------------------
// Scratch (device globals; no allocation allowed)
// ---------------------------------------------------------------------------
__device__ float g_ench [BN * HN];               // leaky(x@We1^T+be1)
__device__ float g_enc  [BN * DN];               // encoded (B,D)
__device__ float g_ts   [DN * HN];               // sorted breakpoint keys
__device__ int   g_sidx [DN * HN];               // sidx[k] = original h of sorted pos k
__device__ float g_sg   [DN * HN];               // sorted 0.4|w1| (0 if degen)
__device__ float g_sgt  [DN * HN];               // sorted 0.4|w1|*t
__device__ float g_sw1  [DN * HN];               // sorted w1
__device__ float g_sb1  [DN * HN];               // sorted b1
__device__ float g_sx   [DN * HN];               // sorted degen 0.4|b1|
__device__ float g_tab  [(size_t)DN * KP1 * 2 * DN]; // interleaved (slope,offs) 67 MB
__device__ int   g_rank [DN * BN];               // [j][b]
__device__ float g_zt   [DN * BN];               // z[j][b]

__device__ __forceinline__ float tanh_fast(float x) {
    float y;
    asm("tanh.approx.f32 %0, %1;" : "=f"(y) : "f"(x));
    return y;
}

// ---------------------------------------------------------------------------
// Kernel 1/2: encoder GEMMs   C[m,n] = act(bias[n] + sum_k A[m,k]*B[n,k])
// ACT: 0 = leaky(0.2), 1 = tanh (accurate — error would propagate)
// ---------------------------------------------------------------------------
template<int ACT>
__global__ void gemm_bias_act(const float* __restrict__ A,
                              const float* __restrict__ Bm,
                              const float* __restrict__ bias,
                              float* __restrict__ C,
                              int M, int N, int K)
{
    __shared__ float As[64][33];
    __shared__ float Bs[64][33];

    const int tid = threadIdx.x;
    const int tx = tid & 15;          // n direction
    const int ty = tid >> 4;          // m direction
    const int bm = blockIdx.y * 64;
    const int bn = blockIdx.x * 64;

    float acc[4][4];
#pragma unroll
    for (int i = 0; i < 4; i++)
#pragma unroll
        for (int j = 0; j < 4; j++) acc[i][j] = 0.0f;

    for (int kc = 0; kc < K; kc += 32) {
#pragma unroll
        for (int l = 0; l < 8; l++) {
            int idx = tid + 256 * l;
            int r = idx >> 5, c = idx & 31;
            As[r][c] = A[(size_t)(bm + r) * K + kc + c];
            Bs[r][c] = Bm[(size_t)(bn + r) * K + kc + c];
        }
        __syncthreads();
#pragma unroll
        for (int kk = 0; kk < 32; kk++) {
            float a[4], b[4];
#pragma unroll
            for (int i = 0; i < 4; i++) a[i] = As[ty * 4 + i][kk];
#pragma unroll
            for (int j = 0; j < 4; j++) b[j] = Bs[tx * 4 + j][kk];
#pragma unroll
            for (int i = 0; i < 4; i++)
#pragma unroll
                for (int j = 0; j < 4; j++)
                    acc[i][j] = fmaf(a[i], b[j], acc[i][j]);
        }
        __syncthreads();
    }

#pragma unroll
    for (int i = 0; i < 4; i++) {
        int m = bm + ty * 4 + i;
#pragma unroll
        for (int j = 0; j < 4; j++) {
            int n = bn + tx * 4 + j;
            float v = acc[i][j] + bias[n];
            if (ACT == 0) v = (v >= 0.0f) ? v : 0.2f * v;
            else          v = tanhf(v);
            C[(size_t)m * N + n] = v;
        }
    }
}

// ---------------------------------------------------------------------------
// Kernel 3: per-j bitonic sort of 512 breakpoints; emit sorted scalar arrays
// and the forward permutation sidx[k] -> original h.
// ---------------------------------------------------------------------------
__global__ void sort_breakpoints(const float* __restrict__ W1s,
                                 const float* __restrict__ b1s)
{
    __shared__ float key[HN];
    __shared__ int   idx[HN];
    const int j = blockIdx.x;
    const int h = threadIdx.x;

    float w1 = W1s[j * HN + h];
    float b1 = b1s[j * HN + h];
    float t  = -b1 / w1;
    bool fin = (w1 != 0.0f) && isfinite(t);
    key[h] = fin ? t : FLT_MAX;
    idx[h] = h;
    __syncthreads();

    for (int size = 2; size <= HN; size <<= 1) {
        for (int stride = size >> 1; stride > 0; stride >>= 1) {
            int p = h ^ stride;
            if (p > h) {
                bool asc = ((h & size) == 0);
                float kh = key[h], kp = key[p];
                if ((kh > kp) == asc) {
                    key[h] = kp; key[p] = kh;
                    int th = idx[h]; idx[h] = idx[p]; idx[p] = th;
                }
            }
            __syncthreads();
        }
    }
    // position h in sorted order holds original index idx[h]
    float tk  = key[h];
    int   ho  = idx[h];
    float w1o = W1s[j * HN + ho];
    float b1o = b1s[j * HN + ho];
    bool  fo  = (tk != FLT_MAX);

    g_ts  [j * HN + h] = tk;
    g_sidx[j * HN + h] = ho;
    g_sw1 [j * HN + h] = w1o;
    g_sb1 [j * HN + h] = b1o;
    float sg = fo ? 0.4f * fabsf(w1o) : 0.0f;
    g_sg  [j * HN + h] = sg;
    g_sgt [j * HN + h] = fo ? sg * tk : 0.0f;
    g_sx  [j * HN + h] = fo ? 0.0f : 0.4f * fabsf(b1o);
}

// ---------------------------------------------------------------------------
// Kernel 4 (fused): stage W2 tile in smem + sorted-order prefix scan + table
// write.  block = (d-tile of 32, j).  threads = 256 = (d:32, chunk:8).
//   tab[j][k][2d] = slope, tab[j][k][2d+1] = offs
// w2_s pitch 513: scan read w2_s[dl*513+hk] has lane-stride 513 = conflict-free.
// ---------------------------------------------------------------------------
#define W2PITCH 513
__global__ __launch_bounds__(256) void build_tables_fused(
    const float* __restrict__ W2s, const float* __restrict__ b2s)
{
    extern __shared__ float sm[];
    float* w2_s   = sm;                          // [32][W2PITCH]
    float* sg_s   = sm + 32 * W2PITCH;
    float* sgt_s  = sg_s  + HN;
    float* sw1_s  = sgt_s + HN;
    float* sb1_s  = sw1_s + HN;
    float* sx_s   = sb1_s + HN;
    int*   sidx_s = (int*)(sx_s + HN);
    float* pg     = (float*)(sidx_s + HN);       // [8][32] each
    float* pq     = pg + 256;
    float* pa     = pq + 256;
    float* pc     = pa + 256;
    float* px     = pc + 256;

    const int j   = blockIdx.y;
    const int d0  = blockIdx.x * 32;
    const int tid = threadIdx.x;

    // Stage 32 W2 rows (coalesced float4 along h)
    const float4* src = reinterpret_cast<const float4*>(
        W2s + ((size_t)j * DN + d0) * HN);
#pragma unroll
    for (int l = 0; l < 16; l++) {
        int idx = l * 256 + tid;
        int d = idx >> 7, hq = idx & 127;
        float4 v = src[d * (HN / 4) + hq];
        float* t = w2_s + d * W2PITCH + hq * 4;
        t[0] = v.x; t[1] = v.y; t[2] = v.z; t[3] = v.w;
    }
    for (int i = tid; i < HN; i += 256) {
        sg_s  [i] = g_sg  [j * HN + i];
        sgt_s [i] = g_sgt [j * HN + i];
        sw1_s [i] = g_sw1 [j * HN + i];
        sb1_s [i] = g_sb1 [j * HN + i];
        sx_s  [i] = g_sx  [j * HN + i];
        sidx_s[i] = g_sidx[j * HN + i];
    }
    __syncthreads();

    const int dl = tid & 31;
    const int c  = tid >> 5;
    const int k0 = c * 64;
    const float* wme = w2_s + dl * W2PITCH;

    // Phase A: chunk partial sums
    float ga = 0.f, qa = 0.f, aa = 0.f, ca = 0.f, xa = 0.f;
#pragma unroll 8
    for (int i = 0; i < 64; i++) {
        int kk = k0 + i;
        float w2 = wme[sidx_s[kk]];
        ga = fmaf(sg_s [kk], w2, ga);
        qa = fmaf(sgt_s[kk], w2, qa);
        aa = fmaf(sw1_s[kk], w2, aa);
        ca = fmaf(sb1_s[kk], w2, ca);
        xa = fmaf(sx_s [kk], w2, xa);
    }
    pg[c * 32 + dl] = ga; pq[c * 32 + dl] = qa; pa[c * 32 + dl] = aa;
    pc[c * 32 + dl] = ca; px[c * 32 + dl] = xa;
    __syncthreads();

    // Totals + carry-in
    float A = 0.f, C = 0.f, G = 0.f, Qt = 0.f, X = 0.f, Pcar = 0.f, Qcar = 0.f;
#pragma unroll
    for (int cc = 0; cc < 8; cc++) {
        float g = pg[cc * 32 + dl], q = pq[cc * 32 + dl];
        A += pa[cc * 32 + dl]; C += pc[cc * 32 + dl]; X += px[cc * 32 + dl];
        G += g; Qt += q;
        if (cc < c) { Pcar += g; Qcar += q; }
    }

    const float base_s = 0.6f * A - G;
    const float base_o = 0.6f * C + Qt + X + b2s[j * DN + d0 + dl];
    float* __restrict__ tj = g_tab + (size_t)j * KP1 * (2 * DN);
    if (c == 0) {
        *reinterpret_cast<float2*>(tj + 2 * (d0 + dl)) = make_float2(base_s, base_o);
    }

    // Phase B: emit 64 table rows per chunk
    float P = Pcar, Q = Qcar;
#pragma unroll 8
    for (int i = 0; i < 64; i++) {
        int kk = k0 + i;
        float w2 = wme[sidx_s[kk]];
        P = fmaf(sg_s [kk], w2, P);
        Q = fmaf(sgt_s[kk], w2, Q);
        float2 v = make_float2(fmaf(2.0f, P, base_s), fmaf(-2.0f, Q, base_o));
        *reinterpret_cast<float2*>(
            tj + (size_t)(kk + 1) * (2 * DN) + 2 * (d0 + dl)) = v;
    }
}

// ---------------------------------------------------------------------------
// Kernel 5: rank(z) per (j,b), breakpoints staged in smem
// ---------------------------------------------------------------------------
__global__ __launch_bounds__(512) void rank_kernel()
{
    __shared__ float ts_s[HN];
    const int j = blockIdx.x;
    const int b = blockIdx.y * 512 + threadIdx.x;
    for (int i = threadIdx.x; i < HN; i += 512) ts_s[i] = g_ts[j * HN + i];
    __syncthreads();

    float z = g_enc[b * DN + j];
    int lo = 0, hi = HN;
    while (lo < hi) {
        int mid = (lo + hi) >> 1;
        if (ts_s[mid] <= z) lo = mid + 1; else hi = mid;
    }
    g_rank[j * BN + b] = lo;
    g_zt  [j * BN + b] = z;
}

// ---------------------------------------------------------------------------
// Kernel 6: evaluate + cumsum + tanh (HW tanh.approx).
// block = 4 b's, 8 warps: warp = (b_local, d-half), 64 d per warp via one
// float4/lane/j on the interleaved 1KB table rows.
// ---------------------------------------------------------------------------
__global__ __launch_bounds__(256) void eval_kernel(float* __restrict__ out)
{
    __shared__ float z_s[DN][4];
    __shared__ int   k_s[DN][4];

    const int b0   = blockIdx.x * 4;
    const int w    = threadIdx.x >> 5;
    const int bl   = w >> 1;               // b_local 0..3
    const int half = w & 1;                // d-half 0/1
    const int lane = threadIdx.x & 31;

    for (int i = threadIdx.x; i < DN * 4; i += 256) {
        int jj = i >> 2, b2 = i & 3;
        z_s[jj][b2] = g_zt  [jj * BN + b0 + b2];
        k_s[jj][b2] = g_rank[jj * BN + b0 + b2];
    }
    __syncthreads();

    const int b = b0 + bl;
    const int toff = half * DN + lane * 4;     // offset into 256-float row
    float a0 = 0.f, a1 = 0.f;

#pragma unroll 8
    for (int j = 0; j < DN; j++) {
        float z = z_s[j][bl];
        int   k = k_s[j][bl];
        const float4 u = *reinterpret_cast<const float4*>(
            g_tab + (size_t)(j * KP1 + k) * (2 * DN) + toff);

        a0 += fmaf(u.x, z, u.y);
        a1 += fmaf(u.z, z, u.w);

        float* op = out + ((size_t)j * BN + b) * DN + half * 64 + 2 * lane;
        *reinterpret_cast<float2*>(op) = make_float2(tanh_fast(a0), tanh_fast(a1));
    }
}

// ---------------------------------------------------------------------------
// Launch — encoder GEMMs forked onto a side stream, overlapping the
// breakpoint-sort + table-build chain; join before rank.
// ---------------------------------------------------------------------------
extern "C" void kernel_launch(void* const* d_in, const int* in_sizes, int n_in,
                              void* d_out, int out_size)
{
    const float* x   = (const float*)d_in[0];   // (2048,128)
    const float* We1 = (const float*)d_in[1];   // (512,128)
    const float* be1 = (const float*)d_in[2];   // (512,)
    const float* We2 = (const float*)d_in[3];   // (128,512)
    const float* be2 = (const float*)d_in[4];   // (128,)
    const float* W1s = (const float*)d_in[5];   // (128,512)
    const float* b1s = (const float*)d_in[6];   // (128,512)
    const float* W2s = (const float*)d_in[7];   // (128,128,512)
    const float* b2s = (const float*)d_in[8];   // (128,128)
    float* out = (float*)d_out;                 // (128,2048,128)

    float* ench; cudaGetSymbolAddress((void**)&ench, g_ench);
    float* enc;  cudaGetSymbolAddress((void**)&enc,  g_enc);

    static cudaStream_t sB = nullptr;
    static cudaEvent_t evFork = nullptr, evJoin = nullptr;
    static int build_smem = 0;
    if (sB == nullptr) {
        cudaStreamCreateWithFlags(&sB, cudaStreamNonBlocking);
        cudaEventCreateWithFlags(&evFork, cudaEventDisableTiming);
        cudaEventCreateWithFlags(&evJoin, cudaEventDisableTiming);
        build_smem = (32 * W2PITCH + 5 * HN + HN /*sidx*/ + 5 * 256) * (int)sizeof(float);
        cudaFuncSetAttribute(build_tables_fused,
                             cudaFuncAttributeMaxDynamicSharedMemorySize, build_smem);
    }

    // Fork: encoder on side stream
    cudaEventRecord(evFork, 0);
    cudaStreamWaitEvent(sB, evFork, 0);
    gemm_bias_act<0><<<dim3(HN / 64, BN / 64), 256, 0, sB>>>(x,    We1, be1, ench, BN, HN, DN);
    gemm_bias_act<1><<<dim3(DN / 64, BN / 64), 256, 0, sB>>>(ench, We2, be2, enc,  BN, DN, HN);
    cudaEventRecord(evJoin, sB);

    // Main stream: sort + fused table build (independent of encoder)
    sort_breakpoints<<<DN, HN>>>(W1s, b1s);
    build_tables_fused<<<dim3(DN / 32, DN), 256, build_smem>>>(W2s, b2s);

    // Join, then rank + fused eval/cumsum/tanh
    cudaStreamWaitEvent(0, evJoin, 0);
    rank_kernel<<<dim3(DN, BN / 512), 512>>>();
    eval_kernel<<<BN / 4, 256>>>(out);
}

// round 8
// speedup vs baseline: 3.0412x; 1.0635x over previous
#include <cuda_runtime.h>
#include <cuda_bf16.h>
#include <cfloat>
#include <math.h>

// Problem dims (fixed by the dataset)
#define BN   2048   // batch B
#define DN   128    // feature dim D (also #decoders and output dim)
#define HN   512    // hidden H
#define KP1  513    // HN + 1 prefix rows

// ---------------------------------------------------------------------------
// Scratch (device globals; no allocation allowed)
// ---------------------------------------------------------------------------
__device__ float  g_ench[BN * HN];               // leaky(x@We1^T+be1)
__device__ float  g_enc [BN * DN];               // encoded (B,D)
__device__ float  g_ts  [DN * HN];               // sorted breakpoint keys
__device__ int    g_pos [DN * HN];               // pos[h] = sorted rank of h
__device__ float4 g_arr4[DN * HN];               // sorted (sg, sgt', w1, b1)
__device__ float  g_tab [(size_t)DN * KP1 * 2 * DN]; // interleaved (slope,offs) 67 MB
__device__ int    g_rank[DN * BN];               // [j][b]
__device__ float  g_zt  [DN * BN];               // z[j][b]

__device__ __forceinline__ float tanh_fast(float x) {
    float y;
    asm("tanh.approx.f32 %0, %1;" : "=f"(y) : "f"(x));
    return y;
}

// ---------------------------------------------------------------------------
// Kernel 1/2: encoder GEMMs   C[m,n] = act(bias[n] + sum_k A[m,k]*B[n,k])
// ACT: 0 = leaky(0.2), 1 = tanh (accurate — error would propagate)
// ---------------------------------------------------------------------------
template<int ACT>
__global__ void gemm_bias_act(const float* __restrict__ A,
                              const float* __restrict__ Bm,
                              const float* __restrict__ bias,
                              float* __restrict__ C,
                              int M, int N, int K)
{
    __shared__ float As[64][33];
    __shared__ float Bs[64][33];

    const int tid = threadIdx.x;
    const int tx = tid & 15;          // n direction
    const int ty = tid >> 4;          // m direction
    const int bm = blockIdx.y * 64;
    const int bn = blockIdx.x * 64;

    float acc[4][4];
#pragma unroll
    for (int i = 0; i < 4; i++)
#pragma unroll
        for (int j = 0; j < 4; j++) acc[i][j] = 0.0f;

    for (int kc = 0; kc < K; kc += 32) {
#pragma unroll
        for (int l = 0; l < 8; l++) {
            int idx = tid + 256 * l;
            int r = idx >> 5, c = idx & 31;
            As[r][c] = A[(size_t)(bm + r) * K + kc + c];
            Bs[r][c] = Bm[(size_t)(bn + r) * K + kc + c];
        }
        __syncthreads();
#pragma unroll
        for (int kk = 0; kk < 32; kk++) {
            float a[4], b[4];
#pragma unroll
            for (int i = 0; i < 4; i++) a[i] = As[ty * 4 + i][kk];
#pragma unroll
            for (int j = 0; j < 4; j++) b[j] = Bs[tx * 4 + j][kk];
#pragma unroll
            for (int i = 0; i < 4; i++)
#pragma unroll
                for (int j = 0; j < 4; j++)
                    acc[i][j] = fmaf(a[i], b[j], acc[i][j]);
        }
        __syncthreads();
    }

#pragma unroll
    for (int i = 0; i < 4; i++) {
        int m = bm + ty * 4 + i;
#pragma unroll
        for (int j = 0; j < 4; j++) {
            int n = bn + tx * 4 + j;
            float v = acc[i][j] + bias[n];
            if (ACT == 0) v = (v >= 0.0f) ? v : 0.2f * v;
            else          v = tanhf(v);
            C[(size_t)m * N + n] = v;
        }
    }
}

// ---------------------------------------------------------------------------
// Kernel 3: per-j bitonic sort of 512 breakpoints.
// Emits g_ts (sorted keys), g_pos (h -> sorted rank), and the packed sorted
// scalar array g_arr4[k] = (sg, sgt', w1, b1) where
//   sg   = finite ? 0.4|w1| : 0
//   sgt' = finite ? sg*t    : 0.4|b1|   (folds the degenerate X term into Qt;
//          degenerate rows sort to the tail and are never ranked-into, so the
//          phase-B corruption of those unreachable rows is harmless)
// ---------------------------------------------------------------------------
__global__ void sort_breakpoints(const float* __restrict__ W1s,
                                 const float* __restrict__ b1s)
{
    __shared__ float key[HN];
    __shared__ int   idx[HN];
    const int j = blockIdx.x;
    const int h = threadIdx.x;

    float w1 = W1s[j * HN + h];
    float b1 = b1s[j * HN + h];
    float t  = -b1 / w1;
    bool fin = (w1 != 0.0f) && isfinite(t);
    key[h] = fin ? t : FLT_MAX;
    idx[h] = h;
    __syncthreads();

    for (int size = 2; size <= HN; size <<= 1) {
        for (int stride = size >> 1; stride > 0; stride >>= 1) {
            int p = h ^ stride;
            if (p > h) {
                bool asc = ((h & size) == 0);
                float kh = key[h], kp = key[p];
                if ((kh > kp) == asc) {
                    key[h] = kp; key[p] = kh;
                    int th = idx[h]; idx[h] = idx[p]; idx[p] = th;
                }
            }
            __syncthreads();
        }
    }
    // position h in sorted order holds original index idx[h]
    float tk  = key[h];
    int   ho  = idx[h];
    float w1o = W1s[j * HN + ho];
    float b1o = b1s[j * HN + ho];
    bool  fo  = (tk != FLT_MAX);

    g_ts [j * HN + h]  = tk;
    g_pos[j * HN + ho] = h;
    float sg  = fo ? 0.4f * fabsf(w1o) : 0.0f;
    float sgt = fo ? sg * tk           : 0.4f * fabsf(b1o);
    g_arr4[j * HN + h] = make_float4(sg, sgt, w1o, b1o);
}

// ---------------------------------------------------------------------------
// Kernel 4 (fused): stage W2 tile PRE-PERMUTED into sorted-k order in smem,
// then chunked prefix scan + direct table write.
//   block = (d-tile of 32, j); threads = 512 = (d:32, chunk:16), chunk len 32.
//   tab[j][k][2d] = slope, tab[j][k][2d+1] = offs
// Inner loops: 1 sequential LDS.32 (w2) + 1 broadcast LDS.128 (arr4) per k.
// ---------------------------------------------------------------------------
#define W2PITCH 513
__global__ __launch_bounds__(512) void build_tables_fused(
    const float* __restrict__ W2s, const float* __restrict__ b2s)
{
    extern __shared__ float sm[];
    float4* arr4_s = (float4*)sm;                    // [512]  (16B aligned)
    float*  w2_s   = sm + 4 * HN;                    // [32][W2PITCH]
    int*    pos_s  = (int*)(w2_s + 32 * W2PITCH);    // [512]
    float*  pg     = (float*)(pos_s + HN);           // [16][32] each
    float*  pq     = pg + 512;
    float*  pa     = pq + 512;
    float*  pc     = pa + 512;

    const int j   = blockIdx.y;
    const int d0  = blockIdx.x * 32;
    const int tid = threadIdx.x;

    // Stage permutation + packed scalars
    {
        int i = tid;                                  // 512 threads, HN=512
        pos_s [i] = g_pos [j * HN + i];
        arr4_s[i] = g_arr4[j * HN + i];
    }
    __syncthreads();

    // Stage 32 W2 rows, scattering into sorted-k positions
    const float4* src = reinterpret_cast<const float4*>(
        W2s + ((size_t)j * DN + d0) * HN);
#pragma unroll
    for (int l = 0; l < 8; l++) {
        int idx = l * 512 + tid;          // 0..4095
        int d = idx >> 7, hq = idx & 127;
        float4 v = src[d * (HN / 4) + hq];
        float* row = w2_s + d * W2PITCH;
        int hb = hq * 4;
        row[pos_s[hb + 0]] = v.x;
        row[pos_s[hb + 1]] = v.y;
        row[pos_s[hb + 2]] = v.z;
        row[pos_s[hb + 3]] = v.w;
    }
    __syncthreads();

    const int dl = tid & 31;
    const int c  = tid >> 5;              // chunk 0..15
    const int k0 = c * 32;
    const float* wme = w2_s + dl * W2PITCH;

    // Phase A: chunk partial sums
    float ga = 0.f, qa = 0.f, aa = 0.f, ca = 0.f;
#pragma unroll
    for (int i = 0; i < 32; i++) {
        int kk = k0 + i;
        float  w2 = wme[kk];
        float4 s  = arr4_s[kk];
        ga = fmaf(s.x, w2, ga);
        qa = fmaf(s.y, w2, qa);
        aa = fmaf(s.z, w2, aa);
        ca = fmaf(s.w, w2, ca);
    }
    pg[c * 32 + dl] = ga; pq[c * 32 + dl] = qa;
    pa[c * 32 + dl] = aa; pc[c * 32 + dl] = ca;
    __syncthreads();

    // Totals + carry-in
    float A = 0.f, C = 0.f, G = 0.f, Qt = 0.f, Pcar = 0.f, Qcar = 0.f;
#pragma unroll
    for (int cc = 0; cc < 16; cc++) {
        float g = pg[cc * 32 + dl], q = pq[cc * 32 + dl];
        A += pa[cc * 32 + dl]; C += pc[cc * 32 + dl];
        G += g; Qt += q;
        if (cc < c) { Pcar += g; Qcar += q; }
    }

    const float base_s = 0.6f * A - G;
    const float base_o = 0.6f * C + Qt + b2s[j * DN + d0 + dl];
    float* __restrict__ tj = g_tab + (size_t)j * KP1 * (2 * DN);
    if (c == 0) {
        *reinterpret_cast<float2*>(tj + 2 * (d0 + dl)) = make_float2(base_s, base_o);
    }

    // Phase B: emit 32 table rows per chunk
    float P = Pcar, Q = Qcar;
#pragma unroll
    for (int i = 0; i < 32; i++) {
        int kk = k0 + i;
        float  w2 = wme[kk];
        float4 s  = arr4_s[kk];
        P = fmaf(s.x, w2, P);
        Q = fmaf(s.y, w2, Q);
        float2 v = make_float2(fmaf(2.0f, P, base_s), fmaf(-2.0f, Q, base_o));
        *reinterpret_cast<float2*>(
            tj + (size_t)(kk + 1) * (2 * DN) + 2 * (d0 + dl)) = v;
    }
}

// ---------------------------------------------------------------------------
// Kernel 5: rank(z) per (j,b), breakpoints staged in smem
// ---------------------------------------------------------------------------
__global__ __launch_bounds__(512) void rank_kernel()
{
    __shared__ float ts_s[HN];
    const int j = blockIdx.x;
    const int b = blockIdx.y * 512 + threadIdx.x;
    for (int i = threadIdx.x; i < HN; i += 512) ts_s[i] = g_ts[j * HN + i];
    __syncthreads();

    float z = g_enc[b * DN + j];
    int lo = 0, hi = HN;
    while (lo < hi) {
        int mid = (lo + hi) >> 1;
        if (ts_s[mid] <= z) lo = mid + 1; else hi = mid;
    }
    g_rank[j * BN + b] = lo;
    g_zt  [j * BN + b] = z;
}

// ---------------------------------------------------------------------------
// Kernel 6: evaluate + cumsum + tanh (HW tanh.approx).
// block = 4 b's, 8 warps: warp = (b_local, d-half), 64 d per warp via one
// float4/lane/j on the interleaved 1KB table rows.
// ---------------------------------------------------------------------------
__global__ __launch_bounds__(256) void eval_kernel(float* __restrict__ out)
{
    __shared__ float z_s[DN][4];
    __shared__ int   k_s[DN][4];

    const int b0   = blockIdx.x * 4;
    const int w    = threadIdx.x >> 5;
    const int bl   = w >> 1;               // b_local 0..3
    const int half = w & 1;                // d-half 0/1
    const int lane = threadIdx.x & 31;

    for (int i = threadIdx.x; i < DN * 4; i += 256) {
        int jj = i >> 2, b2 = i & 3;
        z_s[jj][b2] = g_zt  [jj * BN + b0 + b2];
        k_s[jj][b2] = g_rank[jj * BN + b0 + b2];
    }
    __syncthreads();

    const int b = b0 + bl;
    const int toff = half * DN + lane * 4;     // offset into 256-float row
    float a0 = 0.f, a1 = 0.f;

#pragma unroll 8
    for (int j = 0; j < DN; j++) {
        float z = z_s[j][bl];
        int   k = k_s[j][bl];
        const float4 u = *reinterpret_cast<const float4*>(
            g_tab + (size_t)(j * KP1 + k) * (2 * DN) + toff);

        a0 += fmaf(u.x, z, u.y);
        a1 += fmaf(u.z, z, u.w);

        float* op = out + ((size_t)j * BN + b) * DN + half * 64 + 2 * lane;
        *reinterpret_cast<float2*>(op) = make_float2(tanh_fast(a0), tanh_fast(a1));
    }
}

// ---------------------------------------------------------------------------
// Launch — encoder + rank on side stream (rank needs sort + encoder only),
// overlapping the fused table build; join before eval.
// ---------------------------------------------------------------------------
extern "C" void kernel_launch(void* const* d_in, const int* in_sizes, int n_in,
                              void* d_out, int out_size)
{
    const float* x   = (const float*)d_in[0];   // (2048,128)
    const float* We1 = (const float*)d_in[1];   // (512,128)
    const float* be1 = (const float*)d_in[2];   // (512,)
    const float* We2 = (const float*)d_in[3];   // (128,512)
    const float* be2 = (const float*)d_in[4];   // (128,)
    const float* W1s = (const float*)d_in[5];   // (128,512)
    const float* b1s = (const float*)d_in[6];   // (128,512)
    const float* W2s = (const float*)d_in[7];   // (128,128,512)
    const float* b2s = (const float*)d_in[8];   // (128,128)
    float* out = (float*)d_out;                 // (128,2048,128)

    float* ench; cudaGetSymbolAddress((void**)&ench, g_ench);
    float* enc;  cudaGetSymbolAddress((void**)&enc,  g_enc);

    static cudaStream_t sB = nullptr;
    static cudaEvent_t evFork = nullptr, evSort = nullptr, evJoin = nullptr;
    static int build_smem = 0;
    if (sB == nullptr) {
        cudaStreamCreateWithFlags(&sB, cudaStreamNonBlocking);
        cudaEventCreateWithFlags(&evFork, cudaEventDisableTiming);
        cudaEventCreateWithFlags(&evSort, cudaEventDisableTiming);
        cudaEventCreateWithFlags(&evJoin, cudaEventDisableTiming);
        build_smem = (4 * HN + 32 * W2PITCH + HN /*pos*/ + 4 * 512) * (int)sizeof(float);
        cudaFuncSetAttribute(build_tables_fused,
                             cudaFuncAttributeMaxDynamicSharedMemorySize, build_smem);
    }

    // Fork: encoder on side stream
    cudaEventRecord(evFork, 0);
    cudaStreamWaitEvent(sB, evFork, 0);
    gemm_bias_act<0><<<dim3(HN / 64, BN / 64), 256, 0, sB>>>(x,    We1, be1, ench, BN, HN, DN);
    gemm_bias_act<1><<<dim3(DN / 64, BN / 64), 256, 0, sB>>>(ench, We2, be2, enc,  BN, DN, HN);

    // Main stream: sort (publishes g_ts for rank), then fused table build
    sort_breakpoints<<<DN, HN>>>(W1s, b1s);
    cudaEventRecord(evSort, 0);
    build_tables_fused<<<dim3(DN / 32, DN), 512, build_smem>>>(W2s, b2s);

    // Side stream: rank after encoder + sort — hidden behind build
    cudaStreamWaitEvent(sB, evSort, 0);
    rank_kernel<<<dim3(DN, BN / 512), 512, 0, sB>>>();
    cudaEventRecord(evJoin, sB);

    // Join, then fused eval/cumsum/tanh
    cudaStreamWaitEvent(0, evJoin, 0);
    eval_kernel<<<BN / 4, 256>>>(out);
}

// round 9
// speedup vs baseline: 3.6252x; 1.1920x over previous
#include <cuda_runtime.h>
#include <cuda_bf16.h>
#include <cfloat>
#include <math.h>

// Problem dims (fixed by the dataset)
#define BN   2048   // batch B
#define DN   128    // feature dim D (also #decoders and output dim)
#define HN   512    // hidden H
#define KP1  513    // HN + 1 prefix rows

// ---------------------------------------------------------------------------
// Scratch (device globals; no allocation allowed)
// ---------------------------------------------------------------------------
__device__ float  g_ench[BN * HN];               // leaky(x@We1^T+be1)
__device__ float  g_enc [BN * DN];               // encoded (B,D)
__device__ float  g_ts  [DN * HN];               // sorted breakpoint keys
__device__ int    g_pos [DN * HN];               // pos[h] = sorted rank of h
__device__ float4 g_arr4[DN * HN];               // sorted (sg, sgt', w1, b1)
__device__ float  g_tab [(size_t)DN * KP1 * 2 * DN]; // interleaved (slope,offs) 67 MB
__device__ int    g_rank[DN * BN];               // [j][b]
__device__ float  g_zt  [DN * BN];               // z[j][b]
__device__ float  g_acc [BN * DN];               // cumsum carry between eval halves

__device__ __forceinline__ float tanh_fast(float x) {
    float y;
    asm("tanh.approx.f32 %0, %1;" : "=f"(y) : "f"(x));
    return y;
}

// ---------------------------------------------------------------------------
// Kernel 1/2: encoder GEMMs   C[m,n] = act(bias[n] + sum_k A[m,k]*B[n,k])
// ACT: 0 = leaky(0.2), 1 = tanh (accurate — error would propagate)
// ---------------------------------------------------------------------------
template<int ACT>
__global__ void gemm_bias_act(const float* __restrict__ A,
                              const float* __restrict__ Bm,
                              const float* __restrict__ bias,
                              float* __restrict__ C,
                              int M, int N, int K)
{
    __shared__ float As[64][33];
    __shared__ float Bs[64][33];

    const int tid = threadIdx.x;
    const int tx = tid & 15;          // n direction
    const int ty = tid >> 4;          // m direction
    const int bm = blockIdx.y * 64;
    const int bn = blockIdx.x * 64;

    float acc[4][4];
#pragma unroll
    for (int i = 0; i < 4; i++)
#pragma unroll
        for (int j = 0; j < 4; j++) acc[i][j] = 0.0f;

    for (int kc = 0; kc < K; kc += 32) {
#pragma unroll
        for (int l = 0; l < 8; l++) {
            int idx = tid + 256 * l;
            int r = idx >> 5, c = idx & 31;
            As[r][c] = A[(size_t)(bm + r) * K + kc + c];
            Bs[r][c] = Bm[(size_t)(bn + r) * K + kc + c];
        }
        __syncthreads();
#pragma unroll
        for (int kk = 0; kk < 32; kk++) {
            float a[4], b[4];
#pragma unroll
            for (int i = 0; i < 4; i++) a[i] = As[ty * 4 + i][kk];
#pragma unroll
            for (int j = 0; j < 4; j++) b[j] = Bs[tx * 4 + j][kk];
#pragma unroll
            for (int i = 0; i < 4; i++)
#pragma unroll
                for (int j = 0; j < 4; j++)
                    acc[i][j] = fmaf(a[i], b[j], acc[i][j]);
        }
        __syncthreads();
    }

#pragma unroll
    for (int i = 0; i < 4; i++) {
        int m = bm + ty * 4 + i;
#pragma unroll
        for (int j = 0; j < 4; j++) {
            int n = bn + tx * 4 + j;
            float v = acc[i][j] + bias[n];
            if (ACT == 0) v = (v >= 0.0f) ? v : 0.2f * v;
            else          v = tanhf(v);
            C[(size_t)m * N + n] = v;
        }
    }
}

// ---------------------------------------------------------------------------
// Kernel 3: per-j bitonic sort of 512 breakpoints.
// Emits g_ts (sorted keys), g_pos (h -> sorted rank), and the packed sorted
// scalar array g_arr4[k] = (sg, sgt', w1, b1); degenerate X term folded into
// sgt' (degenerate rows sort to the tail -> never ranked-into).
// ---------------------------------------------------------------------------
__global__ void sort_breakpoints(const float* __restrict__ W1s,
                                 const float* __restrict__ b1s)
{
    __shared__ float key[HN];
    __shared__ int   idx[HN];
    const int j = blockIdx.x;
    const int h = threadIdx.x;

    float w1 = W1s[j * HN + h];
    float b1 = b1s[j * HN + h];
    float t  = -b1 / w1;
    bool fin = (w1 != 0.0f) && isfinite(t);
    key[h] = fin ? t : FLT_MAX;
    idx[h] = h;
    __syncthreads();

    for (int size = 2; size <= HN; size <<= 1) {
        for (int stride = size >> 1; stride > 0; stride >>= 1) {
            int p = h ^ stride;
            if (p > h) {
                bool asc = ((h & size) == 0);
                float kh = key[h], kp = key[p];
                if ((kh > kp) == asc) {
                    key[h] = kp; key[p] = kh;
                    int th = idx[h]; idx[h] = idx[p]; idx[p] = th;
                }
            }
            __syncthreads();
        }
    }
    float tk  = key[h];
    int   ho  = idx[h];
    float w1o = W1s[j * HN + ho];
    float b1o = b1s[j * HN + ho];
    bool  fo  = (tk != FLT_MAX);

    g_ts [j * HN + h]  = tk;
    g_pos[j * HN + ho] = h;
    float sg  = fo ? 0.4f * fabsf(w1o) : 0.0f;
    float sgt = fo ? sg * tk           : 0.4f * fabsf(b1o);
    g_arr4[j * HN + h] = make_float4(sg, sgt, w1o, b1o);
}

// ---------------------------------------------------------------------------
// Kernel 4 (fused): stage W2 tile PRE-PERMUTED into sorted-k order in smem,
// then chunked prefix scan + direct table write.  j = blockIdx.y + j_base.
// ---------------------------------------------------------------------------
#define W2PITCH 513
__global__ __launch_bounds__(512) void build_tables_fused(
    const float* __restrict__ W2s, const float* __restrict__ b2s, int j_base)
{
    extern __shared__ float sm[];
    float4* arr4_s = (float4*)sm;                    // [512]
    float*  w2_s   = sm + 4 * HN;                    // [32][W2PITCH]
    int*    pos_s  = (int*)(w2_s + 32 * W2PITCH);    // [512]
    float*  pg     = (float*)(pos_s + HN);           // [16][32] each
    float*  pq     = pg + 512;
    float*  pa     = pq + 512;
    float*  pc     = pa + 512;

    const int j   = blockIdx.y + j_base;
    const int d0  = blockIdx.x * 32;
    const int tid = threadIdx.x;

    {
        int i = tid;
        pos_s [i] = g_pos [j * HN + i];
        arr4_s[i] = g_arr4[j * HN + i];
    }
    __syncthreads();

    const float4* src = reinterpret_cast<const float4*>(
        W2s + ((size_t)j * DN + d0) * HN);
#pragma unroll
    for (int l = 0; l < 8; l++) {
        int idx = l * 512 + tid;
        int d = idx >> 7, hq = idx & 127;
        float4 v = src[d * (HN / 4) + hq];
        float* row = w2_s + d * W2PITCH;
        int hb = hq * 4;
        row[pos_s[hb + 0]] = v.x;
        row[pos_s[hb + 1]] = v.y;
        row[pos_s[hb + 2]] = v.z;
        row[pos_s[hb + 3]] = v.w;
    }
    __syncthreads();

    const int dl = tid & 31;
    const int c  = tid >> 5;
    const int k0 = c * 32;
    const float* wme = w2_s + dl * W2PITCH;

    float ga = 0.f, qa = 0.f, aa = 0.f, ca = 0.f;
#pragma unroll
    for (int i = 0; i < 32; i++) {
        int kk = k0 + i;
        float  w2 = wme[kk];
        float4 s  = arr4_s[kk];
        ga = fmaf(s.x, w2, ga);
        qa = fmaf(s.y, w2, qa);
        aa = fmaf(s.z, w2, aa);
        ca = fmaf(s.w, w2, ca);
    }
    pg[c * 32 + dl] = ga; pq[c * 32 + dl] = qa;
    pa[c * 32 + dl] = aa; pc[c * 32 + dl] = ca;
    __syncthreads();

    float A = 0.f, C = 0.f, G = 0.f, Qt = 0.f, Pcar = 0.f, Qcar = 0.f;
#pragma unroll
    for (int cc = 0; cc < 16; cc++) {
        float g = pg[cc * 32 + dl], q = pq[cc * 32 + dl];
        A += pa[cc * 32 + dl]; C += pc[cc * 32 + dl];
        G += g; Qt += q;
        if (cc < c) { Pcar += g; Qcar += q; }
    }

    const float base_s = 0.6f * A - G;
    const float base_o = 0.6f * C + Qt + b2s[j * DN + d0 + dl];
    float* __restrict__ tj = g_tab + (size_t)j * KP1 * (2 * DN);
    if (c == 0) {
        *reinterpret_cast<float2*>(tj + 2 * (d0 + dl)) = make_float2(base_s, base_o);
    }

    float P = Pcar, Q = Qcar;
#pragma unroll
    for (int i = 0; i < 32; i++) {
        int kk = k0 + i;
        float  w2 = wme[kk];
        float4 s  = arr4_s[kk];
        P = fmaf(s.x, w2, P);
        Q = fmaf(s.y, w2, Q);
        float2 v = make_float2(fmaf(2.0f, P, base_s), fmaf(-2.0f, Q, base_o));
        *reinterpret_cast<float2*>(
            tj + (size_t)(kk + 1) * (2 * DN) + 2 * (d0 + dl)) = v;
    }
}

// ---------------------------------------------------------------------------
// Kernel 5: rank(z) per (j,b), breakpoints staged in smem
// ---------------------------------------------------------------------------
__global__ __launch_bounds__(512) void rank_kernel()
{
    __shared__ float ts_s[HN];
    const int j = blockIdx.x;
    const int b = blockIdx.y * 512 + threadIdx.x;
    for (int i = threadIdx.x; i < HN; i += 512) ts_s[i] = g_ts[j * HN + i];
    __syncthreads();

    float z = g_enc[b * DN + j];
    int lo = 0, hi = HN;
    while (lo < hi) {
        int mid = (lo + hi) >> 1;
        if (ts_s[mid] <= z) lo = mid + 1; else hi = mid;
    }
    g_rank[j * BN + b] = lo;
    g_zt  [j * BN + b] = z;
}

// ---------------------------------------------------------------------------
// Kernel 6: evaluate + cumsum + tanh over a j-half [J0, J0+64).
// block = 4 b's, 8 warps: warp = (b_local, d-half), 64 d per warp.
// Streaming stores (__stcs) for out/carry keep table rows L2-resident;
// __ldg for table reads.  Carry through g_acc makes FP order exact.
// ---------------------------------------------------------------------------
template<int J0, bool LOAD_CARRY, bool SAVE_CARRY>
__global__ __launch_bounds__(256) void eval_kernel(float* __restrict__ out)
{
    __shared__ float z_s[64][4];
    __shared__ int   k_s[64][4];

    const int b0   = blockIdx.x * 4;
    const int w    = threadIdx.x >> 5;
    const int bl   = w >> 1;               // b_local 0..3
    const int half = w & 1;                // d-half 0/1
    const int lane = threadIdx.x & 31;

    for (int i = threadIdx.x; i < 64 * 4; i += 256) {
        int jj = i >> 2, b2 = i & 3;
        z_s[jj][b2] = g_zt  [(J0 + jj) * BN + b0 + b2];
        k_s[jj][b2] = g_rank[(J0 + jj) * BN + b0 + b2];
    }
    __syncthreads();

    const int b = b0 + bl;
    const int toff = half * DN + lane * 4;     // offset into 256-float row
    const size_t cidx = (size_t)b * DN + half * 64 + 2 * lane;

    float a0 = 0.f, a1 = 0.f;
    if (LOAD_CARRY) {
        float2 cv = *reinterpret_cast<const float2*>(g_acc + cidx);
        a0 = cv.x; a1 = cv.y;
    }

#pragma unroll 8
    for (int jj = 0; jj < 64; jj++) {
        float z = z_s[jj][bl];
        int   k = k_s[jj][bl];
        const float4 u = __ldg(reinterpret_cast<const float4*>(
            g_tab + (size_t)((J0 + jj) * KP1 + k) * (2 * DN) + toff));

        a0 += fmaf(u.x, z, u.y);
        a1 += fmaf(u.z, z, u.w);

        float* op = out + ((size_t)(J0 + jj) * BN + b) * DN + half * 64 + 2 * lane;
        __stcs(reinterpret_cast<float2*>(op),
               make_float2(tanh_fast(a0), tanh_fast(a1)));
    }

    if (SAVE_CARRY) {
        __stcs(reinterpret_cast<float2*>(g_acc + cidx), make_float2(a0, a1));
    }
}

// ---------------------------------------------------------------------------
// Launch — pipeline:
//   sB  : encoder GEMMs -> rank (after sort) -> eval(j<64) (after buildA)
//   main: sort -> buildA (j<64) -> buildB (j>=64) -> eval(j>=64) (after eval1)
// ---------------------------------------------------------------------------
extern "C" void kernel_launch(void* const* d_in, const int* in_sizes, int n_in,
                              void* d_out, int out_size)
{
    const float* x   = (const float*)d_in[0];   // (2048,128)
    const float* We1 = (const float*)d_in[1];   // (512,128)
    const float* be1 = (const float*)d_in[2];   // (512,)
    const float* We2 = (const float*)d_in[3];   // (128,512)
    const float* be2 = (const float*)d_in[4];   // (128,)
    const float* W1s = (const float*)d_in[5];   // (128,512)
    const float* b1s = (const float*)d_in[6];   // (128,512)
    const float* W2s = (const float*)d_in[7];   // (128,128,512)
    const float* b2s = (const float*)d_in[8];   // (128,128)
    float* out = (float*)d_out;                 // (128,2048,128)

    float* ench; cudaGetSymbolAddress((void**)&ench, g_ench);
    float* enc;  cudaGetSymbolAddress((void**)&enc,  g_enc);

    static cudaStream_t sB = nullptr;
    static cudaEvent_t evFork = nullptr, evSort = nullptr,
                       evBuildA = nullptr, evEval1 = nullptr;
    static int build_smem = 0;
    if (sB == nullptr) {
        cudaStreamCreateWithFlags(&sB, cudaStreamNonBlocking);
        cudaEventCreateWithFlags(&evFork,   cudaEventDisableTiming);
        cudaEventCreateWithFlags(&evSort,   cudaEventDisableTiming);
        cudaEventCreateWithFlags(&evBuildA, cudaEventDisableTiming);
        cudaEventCreateWithFlags(&evEval1,  cudaEventDisableTiming);
        build_smem = (4 * HN + 32 * W2PITCH + HN /*pos*/ + 4 * 512) * (int)sizeof(float);
        cudaFuncSetAttribute(build_tables_fused,
                             cudaFuncAttributeMaxDynamicSharedMemorySize, build_smem);
    }

    // Fork: encoder on side stream
    cudaEventRecord(evFork, 0);
    cudaStreamWaitEvent(sB, evFork, 0);
    gemm_bias_act<0><<<dim3(HN / 64, BN / 64), 256, 0, sB>>>(x,    We1, be1, ench, BN, HN, DN);
    gemm_bias_act<1><<<dim3(DN / 64, BN / 64), 256, 0, sB>>>(ench, We2, be2, enc,  BN, DN, HN);

    // Main stream: sort, then first-half table build
    sort_breakpoints<<<DN, HN>>>(W1s, b1s);
    cudaEventRecord(evSort, 0);
    build_tables_fused<<<dim3(DN / 32, 64), 512, build_smem>>>(W2s, b2s, 0);
    cudaEventRecord(evBuildA, 0);
    // Second-half build overlaps eval1 (different streams, different j rows)
    build_tables_fused<<<dim3(DN / 32, 64), 512, build_smem>>>(W2s, b2s, 64);

    // Side stream: rank (needs sort + encoder), then eval of first j-half
    cudaStreamWaitEvent(sB, evSort, 0);
    rank_kernel<<<dim3(DN, BN / 512), 512, 0, sB>>>();
    cudaStreamWaitEvent(sB, evBuildA, 0);
    eval_kernel<0, false, true><<<BN / 4, 256, 0, sB>>>(out);
    cudaEventRecord(evEval1, sB);

    // Main: second j-half eval after buildB (in-order) + eval1 carry
    cudaStreamWaitEvent(0, evEval1, 0);
    eval_kernel<64, true, false><<<BN / 4, 256>>>(out);
}